// round 3
// baseline (speedup 1.0000x reference)
#include <cuda_runtime.h>
#include <math_constants.h>

// TropConv2D: x (8,32,32,32) f32, w (288,64) f32 (logical (1,1,1,K,F)), bias (64,)
// out (8,30,30,64): max_k(p_k + w_kf) - min_k(p_k + w_kf) + bias_f
// K = 3*3*32 = 288 with k = (i*3 + j)*32 + c  (TF extract_patches order, channel fastest)

#define B_  8
#define H_  32
#define W_  32
#define C_  32
#define HO_ 30
#define WO_ 30
#define F_  64

__global__ __launch_bounds__(256, 4)
void trop_conv2d_kernel(const float* __restrict__ x,
                        const float* __restrict__ w,
                        const float* __restrict__ bias,
                        float* __restrict__ out)
{
    const int tid  = blockIdx.x * 256 + threadIdx.x;
    const int warp = tid >> 5;
    const int lane = tid & 31;

    // lane -> (pixel within warp, filter quad)
    const int pixSel = lane >> 4;        // 0..1
    const int fi     = lane & 15;        // 0..15
    const int fb     = fi << 2;          // f base: 0,4,...,60

    const int pix = warp * 2 + pixSel;   // 0..7199  (exactly 3600 warps)
    const int b   = pix / (HO_ * WO_);
    const int r   = pix - b * (HO_ * WO_);
    const int ho  = r / WO_;
    const int wo  = r - ho * WO_;

    const float* xbase = x + (((b * H_) + ho) * W_ + wo) * C_;

    float mx0 = -CUDART_INF_F, mx1 = -CUDART_INF_F, mx2 = -CUDART_INF_F, mx3 = -CUDART_INF_F;
    float mn0 =  CUDART_INF_F, mn1 =  CUDART_INF_F, mn2 =  CUDART_INF_F, mn3 =  CUDART_INF_F;

    #pragma unroll 1
    for (int ij = 0; ij < 9; ij++) {
        const int i = ij / 3;
        const int j = ij - i * 3;
        const float* xr = xbase + (i * W_ + j) * C_;       // 32 contiguous channels
        const float* wr = w + (ij * C_) * F_ + fb;         // w[(ij*32 + c)*64 + fb]

        #pragma unroll
        for (int c = 0; c < C_; c += 4) {
            const float4 p  = *reinterpret_cast<const float4*>(xr + c);
            const float4 w0 = *reinterpret_cast<const float4*>(wr + (c + 0) * F_);
            const float4 w1 = *reinterpret_cast<const float4*>(wr + (c + 1) * F_);
            const float4 w2 = *reinterpret_cast<const float4*>(wr + (c + 2) * F_);
            const float4 w3 = *reinterpret_cast<const float4*>(wr + (c + 3) * F_);

            float s;
            // k = base + c + 0
            s = p.x + w0.x; mx0 = fmaxf(mx0, s); mn0 = fminf(mn0, s);
            s = p.x + w0.y; mx1 = fmaxf(mx1, s); mn1 = fminf(mn1, s);
            s = p.x + w0.z; mx2 = fmaxf(mx2, s); mn2 = fminf(mn2, s);
            s = p.x + w0.w; mx3 = fmaxf(mx3, s); mn3 = fminf(mn3, s);
            // k = base + c + 1
            s = p.y + w1.x; mx0 = fmaxf(mx0, s); mn0 = fminf(mn0, s);
            s = p.y + w1.y; mx1 = fmaxf(mx1, s); mn1 = fminf(mn1, s);
            s = p.y + w1.z; mx2 = fmaxf(mx2, s); mn2 = fminf(mn2, s);
            s = p.y + w1.w; mx3 = fmaxf(mx3, s); mn3 = fminf(mn3, s);
            // k = base + c + 2
            s = p.z + w2.x; mx0 = fmaxf(mx0, s); mn0 = fminf(mn0, s);
            s = p.z + w2.y; mx1 = fmaxf(mx1, s); mn1 = fminf(mn1, s);
            s = p.z + w2.z; mx2 = fmaxf(mx2, s); mn2 = fminf(mn2, s);
            s = p.z + w2.w; mx3 = fmaxf(mx3, s); mn3 = fminf(mn3, s);
            // k = base + c + 3
            s = p.w + w3.x; mx0 = fmaxf(mx0, s); mn0 = fminf(mn0, s);
            s = p.w + w3.y; mx1 = fmaxf(mx1, s); mn1 = fminf(mn1, s);
            s = p.w + w3.z; mx2 = fmaxf(mx2, s); mn2 = fminf(mn2, s);
            s = p.w + w3.w; mx3 = fmaxf(mx3, s); mn3 = fminf(mn3, s);
        }
    }

    const float4 bb = *reinterpret_cast<const float4*>(bias + fb);
    float4 o;
    o.x = mx0 - mn0 + bb.x;
    o.y = mx1 - mn1 + bb.y;
    o.z = mx2 - mn2 + bb.z;
    o.w = mx3 - mn3 + bb.w;
    *reinterpret_cast<float4*>(out + pix * F_ + fb) = o;
}

extern "C" void kernel_launch(void* const* d_in, const int* in_sizes, int n_in,
                              void* d_out, int out_size)
{
    const float* x    = (const float*)d_in[0];   // 8*32*32*32 = 262144
    const float* w    = (const float*)d_in[1];   // 288*64     = 18432
    const float* bias = (const float*)d_in[2];   // 64
    float* out = (float*)d_out;                  // 8*30*30*64 = 460800

    // 7200 pixels, 2 pixels/warp -> 3600 warps -> 450 blocks of 256 threads (exact)
    trop_conv2d_kernel<<<450, 256>>>(x, w, bias, out);
}

// round 5
// speedup vs baseline: 1.3250x; 1.3250x over previous
#include <cuda_runtime.h>
#include <cuda_fp16.h>
#include <math_constants.h>

// TropConv2D: x (8,32,32,32) f32, w (288,64) f32, bias (64) f32
// out (8,30,30,64) f32: max_k(p_k + w_kf) - min_k(p_k + w_kf) + bias_f
// K = 3*3*32, k = (ii*3 + jj)*32 + c (channel fastest)
//
// Strategy: fp16 packed (channel pairs) -> HADD2 + HMNMX2 halve the scalar-pipe
// work vs fp32. Prepass converts x -> half and transposes w into channel-pair
// half2 layout so the hot loop has ZERO conversion/unpack instructions.

#define HO_ 30
#define WO_ 30

// Scratch (static __device__ arrays are allowed; no allocation)
__device__ uint2   g_x4[65536];    // x as half, 4 consecutive channels per entry
__device__ __half2 g_wp2[9216];    // [kp][f] = (w[2kp][f], w[2kp+1][f]), kp<144, f<64

__global__ __launch_bounds__(256)
void trop_prepass(const float4* __restrict__ x4, const float* __restrict__ w)
{
    const int t = blockIdx.x * 256 + threadIdx.x;   // grid covers exactly 74752
    if (t < 65536) {
        float4 v = x4[t];
        __half2 h01 = __floats2half2_rn(v.x, v.y);  // low = even channel
        __half2 h23 = __floats2half2_rn(v.z, v.w);
        uint2 u;
        u.x = *reinterpret_cast<unsigned int*>(&h01);
        u.y = *reinterpret_cast<unsigned int*>(&h23);
        g_x4[t] = u;
    } else {
        const int wi = t - 65536;                   // 0..9215
        const int kp = wi >> 6;
        const int f  = wi & 63;
        g_wp2[wi] = __floats2half2_rn(w[(2 * kp) * 64 + f],
                                      w[(2 * kp + 1) * 64 + f]);
    }
}

__global__ __launch_bounds__(32)
void trop_main(const float* __restrict__ bias, float* __restrict__ out)
{
    const int g = blockIdx.x;        // warp id, 0..1799; 4 pixels per warp
    const int j = threadIdx.x;       // lane -> filters j and j+32

    // Pixel base offsets (element index into half-x array)
    int xoff[4];
    #pragma unroll
    for (int px = 0; px < 4; px++) {
        const int pix = g * 4 + px;
        const int b  = pix / (HO_ * WO_);
        const int r  = pix - b * (HO_ * WO_);
        const int ho = r / WO_;
        const int wo = r - ho * WO_;
        xoff[px] = ((b * 32 + ho) * 32 + wo) * 32;
    }

    const __half2 PINF = __float2half2_rn(CUDART_INF_F);
    const __half2 NINF = __float2half2_rn(-CUDART_INF_F);

    __half2 mxA[4], mnA[4], mxB[4], mnB[4];
    #pragma unroll
    for (int px = 0; px < 4; px++) {
        mxA[px] = NINF; mxB[px] = NINF;
        mnA[px] = PINF; mnB[px] = PINF;
    }

    #pragma unroll 1
    for (int ij = 0; ij < 9; ij++) {
        const int ii  = ij / 3;
        const int jj  = ij - ii * 3;
        const int tap = (ii * 32 + jj) * 32;               // elem offset of this window tap
        const __half2* wbase = g_wp2 + ij * 1024 + j;      // kp base = ij*16, stride 64/kp

        #pragma unroll
        for (int cs = 0; cs < 8; cs++) {
            // w for channel pairs (kp0, kp0+1), filters j and j+32
            const __half2 wA0 = wbase[cs * 128];
            const __half2 wB0 = wbase[cs * 128 + 32];
            const __half2 wA1 = wbase[cs * 128 + 64];
            const __half2 wB1 = wbase[cs * 128 + 96];

            #pragma unroll
            for (int px = 0; px < 4; px++) {
                const uint2 pv = g_x4[(xoff[px] + tap + cs * 4) >> 2];
                const __half2 p01 = *reinterpret_cast<const __half2*>(&pv.x);
                const __half2 p23 = *reinterpret_cast<const __half2*>(&pv.y);

                __half2 s;
                s = __hadd2(p01, wA0); mxA[px] = __hmax2(mxA[px], s); mnA[px] = __hmin2(mnA[px], s);
                s = __hadd2(p01, wB0); mxB[px] = __hmax2(mxB[px], s); mnB[px] = __hmin2(mnB[px], s);
                s = __hadd2(p23, wA1); mxA[px] = __hmax2(mxA[px], s); mnA[px] = __hmin2(mnA[px], s);
                s = __hadd2(p23, wB1); mxB[px] = __hmax2(mxB[px], s); mnB[px] = __hmin2(mnB[px], s);
            }
        }
    }

    // Epilogue in fp32
    const float bj  = bias[j];
    const float bj2 = bias[j + 32];
    #pragma unroll
    for (int px = 0; px < 4; px++) {
        const float mA = fmaxf(__low2float(mxA[px]), __high2float(mxA[px]));
        const float nA = fminf(__low2float(mnA[px]), __high2float(mnA[px]));
        const float mB = fmaxf(__low2float(mxB[px]), __high2float(mxB[px]));
        const float nB = fminf(__low2float(mnB[px]), __high2float(mnB[px]));
        const int pix = g * 4 + px;
        out[pix * 64 + j]      = mA - nA + bj;
        out[pix * 64 + j + 32] = mB - nB + bj2;
    }
}

extern "C" void kernel_launch(void* const* d_in, const int* in_sizes, int n_in,
                              void* d_out, int out_size)
{
    const float* x    = (const float*)d_in[0];   // 262144
    const float* w    = (const float*)d_in[1];   // 18432
    const float* bias = (const float*)d_in[2];   // 64
    float* out = (float*)d_out;                  // 460800

    // 65536 float4 x-chunks + 9216 w channel-pairs = 74752 = 292 * 256
    trop_prepass<<<292, 256>>>((const float4*)x, w);
    // 7200 pixels, 4 per warp -> 1800 single-warp blocks (12.2/SM, 7% tail)
    trop_main<<<1800, 32>>>(bias, out);
}

// round 6
// speedup vs baseline: 1.7084x; 1.2894x over previous
#include <cuda_runtime.h>
#include <cuda_fp16.h>
#include <math_constants.h>

// TropConv2D: x (8,32,32,32) f32, w (288,64) f32, bias (64) f32
// out (8,30,30,64) f32: max_k(p_k + w_kf) - min_k(p_k + w_kf) + bias_f
// K = 3*3*32, k = (ii*3 + jj)*32 + c (channel fastest)
//
// fp16x2 semiring (HADD2/HMNMX2). w repacked into uint4 (4 channel-pairs) and
// staged in smem; x repacked into uint4 (8 channels) read via broadcast LDG.

#define HO_ 30
#define WO_ 30

__device__ uint4 g_x8[32768];   // x as half, 8 consecutive channels per entry
__device__ uint4 g_w4[2304];    // [ij][q][f]: channel-pairs 4q..4q+3 of tap ij, filter f

__device__ __forceinline__ unsigned packh2(float a, float b) {
    __half2 h = __floats2half2_rn(a, b);
    return *reinterpret_cast<unsigned*>(&h);
}
__device__ __forceinline__ __half2 as_h2(unsigned u) {
    return *reinterpret_cast<__half2*>(&u);
}

__global__ __launch_bounds__(256)
void trop_prepass(const float4* __restrict__ x4, const float* __restrict__ w)
{
    const int t = blockIdx.x * 256 + threadIdx.x;   // grid covers 35072 = 137*256
    if (t < 32768) {
        const float4 a = x4[2 * t];
        const float4 b = x4[2 * t + 1];
        uint4 u;
        u.x = packh2(a.x, a.y);
        u.y = packh2(a.z, a.w);
        u.z = packh2(b.x, b.y);
        u.w = packh2(b.z, b.w);
        g_x8[t] = u;
    } else if (t < 35072) {
        const int wi = t - 32768;        // 0..2303
        const int f  = wi & 63;
        const int q  = (wi >> 6) & 3;
        const int ij = wi >> 8;
        const int k0 = ij * 32 + q * 8;  // first of 8 channels in this group
        uint4 u;
        u.x = packh2(w[(k0 + 0) * 64 + f], w[(k0 + 1) * 64 + f]);
        u.y = packh2(w[(k0 + 2) * 64 + f], w[(k0 + 3) * 64 + f]);
        u.z = packh2(w[(k0 + 4) * 64 + f], w[(k0 + 5) * 64 + f]);
        u.w = packh2(w[(k0 + 6) * 64 + f], w[(k0 + 7) * 64 + f]);
        g_w4[wi] = u;
    }
}

__global__ __launch_bounds__(256)
void trop_main(const float* __restrict__ bias, float* __restrict__ out)
{
    __shared__ uint4 ws[2304];   // 36 KB: [ij*256 + q*64 + f]

    const int t = threadIdx.x;
    #pragma unroll
    for (int i = 0; i < 9; i++) ws[t + i * 256] = g_w4[t + i * 256];
    __syncthreads();

    const int warp = t >> 5;
    const int lane = t & 31;              // filter fA = lane, fB = lane + 32
    const int pix0 = (blockIdx.x * 8 + warp) * 2;

    int xb[2];
    #pragma unroll
    for (int px = 0; px < 2; px++) {
        const int pix = pix0 + px;
        const int b  = pix / (HO_ * WO_);
        const int r  = pix - b * (HO_ * WO_);
        const int ho = r / WO_;
        const int wo = r - ho * WO_;
        xb[px] = ((b * 32 + ho) * 32 + wo) * 4;   // uint4 index (8 halves each)
    }

    const __half2 PINF = __float2half2_rn(CUDART_INF_F);
    const __half2 NINF = __float2half2_rn(-CUDART_INF_F);
    __half2 mxA[2], mnA[2], mxB[2], mnB[2];
    #pragma unroll
    for (int px = 0; px < 2; px++) {
        mxA[px] = NINF; mxB[px] = NINF;
        mnA[px] = PINF; mnB[px] = PINF;
    }

    #pragma unroll
    for (int ij = 0; ij < 9; ij++) {
        const int ii  = ij / 3;
        const int jj  = ij - ii * 3;
        const int tap = (ii * 32 + jj) * 4;       // uint4 offset of this window tap

        #pragma unroll
        for (int q = 0; q < 4; q++) {
            const uint4 wAu = ws[ij * 256 + q * 64 + lane];
            const uint4 wBu = ws[ij * 256 + q * 64 + lane + 32];
            const __half2 wA0 = as_h2(wAu.x), wA1 = as_h2(wAu.y),
                          wA2 = as_h2(wAu.z), wA3 = as_h2(wAu.w);
            const __half2 wB0 = as_h2(wBu.x), wB1 = as_h2(wBu.y),
                          wB2 = as_h2(wBu.z), wB3 = as_h2(wBu.w);

            #pragma unroll
            for (int px = 0; px < 2; px++) {
                const uint4 xv = g_x8[xb[px] + tap + q];    // broadcast load
                const __half2 p0 = as_h2(xv.x), p1 = as_h2(xv.y),
                              p2 = as_h2(xv.z), p3 = as_h2(xv.w);
                __half2 s;
                s = __hadd2(p0, wA0); mxA[px] = __hmax2(mxA[px], s); mnA[px] = __hmin2(mnA[px], s);
                s = __hadd2(p1, wA1); mxA[px] = __hmax2(mxA[px], s); mnA[px] = __hmin2(mnA[px], s);
                s = __hadd2(p2, wA2); mxA[px] = __hmax2(mxA[px], s); mnA[px] = __hmin2(mnA[px], s);
                s = __hadd2(p3, wA3); mxA[px] = __hmax2(mxA[px], s); mnA[px] = __hmin2(mnA[px], s);
                s = __hadd2(p0, wB0); mxB[px] = __hmax2(mxB[px], s); mnB[px] = __hmin2(mnB[px], s);
                s = __hadd2(p1, wB1); mxB[px] = __hmax2(mxB[px], s); mnB[px] = __hmin2(mnB[px], s);
                s = __hadd2(p2, wB2); mxB[px] = __hmax2(mxB[px], s); mnB[px] = __hmin2(mnB[px], s);
                s = __hadd2(p3, wB3); mxB[px] = __hmax2(mxB[px], s); mnB[px] = __hmin2(mnB[px], s);
            }
        }
    }

    const float bA = bias[lane];
    const float bB = bias[lane + 32];
    #pragma unroll
    for (int px = 0; px < 2; px++) {
        const float mA = fmaxf(__low2float(mxA[px]), __high2float(mxA[px]));
        const float nA = fminf(__low2float(mnA[px]), __high2float(mnA[px]));
        const float mB = fmaxf(__low2float(mxB[px]), __high2float(mxB[px]));
        const float nB = fminf(__low2float(mnB[px]), __high2float(mnB[px]));
        const int pix = pix0 + px;
        out[pix * 64 + lane]      = mA - nA + bA;
        out[pix * 64 + lane + 32] = mB - nB + bB;
    }
}

extern "C" void kernel_launch(void* const* d_in, const int* in_sizes, int n_in,
                              void* d_out, int out_size)
{
    const float* x    = (const float*)d_in[0];   // 262144
    const float* w    = (const float*)d_in[1];   // 18432
    const float* bias = (const float*)d_in[2];   // 64
    float* out = (float*)d_out;                  // 460800

    trop_prepass<<<137, 256>>>((const float4*)x, w);
    // 7200 pixels, 2/warp, 8 warps/block -> 450 blocks, 3600 warps (24.3/SM)
    trop_main<<<450, 256>>>(bias, out);
}